// round 8
// baseline (speedup 1.0000x reference)
#include <cuda_runtime.h>
#include <math.h>

#define NN   512
#define CSd  384
#define CZd  128
#define Hd   12
#define Cd   16
#define PQd  4
#define PVd  8
#define DE   28
#define CATd 2017
#define MPROJ 1152
#define KSPLIT 8

typedef unsigned long long ull;

// ---------------- packed f32x2 helpers ----------------
__device__ __forceinline__ void ffma2(ull& acc, ull a, ull b) {
    asm("fma.rn.f32x2 %0, %1, %2, %0;" : "+l"(acc) : "l"(a), "l"(b));
}
__device__ __forceinline__ ull pk2(float x, float y) {
    ull r; asm("mov.b64 %0, {%1,%2};" : "=l"(r) : "f"(x), "f"(y)); return r;
}
__device__ __forceinline__ void upk2(ull v, float& x, float& y) {
    asm("mov.b64 {%0,%1}, %2;" : "=f"(x), "=f"(y) : "l"(v));
}

// ---------------- device scratch ----------------
__device__ float g_Wcat[MPROJ * CSd];
__device__ float g_P[MPROJ * NN];
__device__ float g_qe[Hd * DE * NN];
__device__ float g_ke[Hd * DE * NN];
__device__ float g_qn[Hd * NN];
__device__ float g_kn[Hd * NN];
__device__ float g_vr[Hd * Cd * NN];
__device__ float g_vg[3 * Hd * PVd * NN];
__device__ float g_Lqk[Hd * NN * NN];        // qk - dist partial [h][i][j]
__device__ float g_bias[Hd * NN * NN];       // bias [h][i][j]
__device__ float g_A[NN * Hd * NN];          // probs [i][h][j]
__device__ float g_cat[CATd * NN];
__device__ float g_part[KSPLIT * CSd * NN];

// ---------------- weight concat ----------------
__global__ void concat_w(const float* __restrict__ Wq, const float* __restrict__ Wk,
                         const float* __restrict__ Wv, const float* __restrict__ Wqp,
                         const float* __restrict__ Wkp, const float* __restrict__ Wvp) {
    int idx = blockIdx.x * 256 + threadIdx.x;
    if (idx >= MPROJ * CSd) return;
    int row = idx / CSd, c = idx % CSd;
    float v;
    if      (row < 192) v = Wq [(row      ) * CSd + c];
    else if (row < 384) v = Wk [(row - 192) * CSd + c];
    else if (row < 576) v = Wv [(row - 384) * CSd + c];
    else if (row < 720) v = Wqp[(row - 576) * CSd + c];
    else if (row < 864) v = Wkp[(row - 720) * CSd + c];
    else                v = Wvp[(row - 864) * CSd + c];
    g_Wcat[idx] = v;
}

// ---------------- tiled GEMM with split-K, pre-packed B ----------------
__global__ __launch_bounds__(256) void gemm64(const float* __restrict__ A,
                                              const float* __restrict__ B,
                                              float* __restrict__ C,
                                              int M, int Nc, int K) {
    int nb = blockIdx.x, mb = blockIdx.y, zb = blockIdx.z;
    int Kc = (K + gridDim.z - 1) / gridDim.z;
    int k0 = zb * Kc;
    int kend = min(K, k0 + Kc);

    __shared__ float As[16][64];
    __shared__ ull   Bs2[16][64];

    int tid = threadIdx.x;
    int ty = tid >> 4, tx = tid & 15;
    ull acc2[2][4];
#pragma unroll
    for (int u = 0; u < 2; ++u)
#pragma unroll
        for (int v = 0; v < 4; ++v) acc2[u][v] = 0ull;

    for (int kk = k0; kk < kend; kk += 16) {
#pragma unroll
        for (int l = 0; l < 4; ++l) {
            int e = tid + l * 256;
            int m = e >> 4, k = e & 15;
            As[k][m] = (kk + k < kend) ? A[(size_t)(mb * 64 + m) * K + kk + k] : 0.f;
        }
#pragma unroll
        for (int l = 0; l < 4; ++l) {
            int e = tid + l * 256;
            int k = e >> 6, n = e & 63;
            float v = (kk + k < kend) ? B[(size_t)(kk + k) * Nc + nb * 64 + n] : 0.f;
            Bs2[k][n] = pk2(v, v);
        }
        __syncthreads();
#pragma unroll
        for (int k = 0; k < 16; ++k) {
            const ull* a2 = (const ull*)&As[k][ty * 4];
            ull a0 = a2[0], a1 = a2[1];
            ull b0 = Bs2[k][tx * 4], b1 = Bs2[k][tx * 4 + 1];
            ull b2 = Bs2[k][tx * 4 + 2], b3 = Bs2[k][tx * 4 + 3];
            ffma2(acc2[0][0], a0, b0); ffma2(acc2[0][1], a0, b1);
            ffma2(acc2[0][2], a0, b2); ffma2(acc2[0][3], a0, b3);
            ffma2(acc2[1][0], a1, b0); ffma2(acc2[1][1], a1, b1);
            ffma2(acc2[1][2], a1, b2); ffma2(acc2[1][3], a1, b3);
        }
        __syncthreads();
    }
    float* Cz = C + (size_t)zb * M * Nc;
#pragma unroll
    for (int u = 0; u < 2; ++u)
#pragma unroll
        for (int v = 0; v < 4; ++v) {
            float lo, hi;
            upk2(acc2[u][v], lo, hi);
            Cz[(size_t)(mb * 64 + ty * 4 + u * 2    ) * Nc + nb * 64 + tx * 4 + v] = lo;
            Cz[(size_t)(mb * 64 + ty * 4 + u * 2 + 1) * Nc + nb * 64 + tx * 4 + v] = hi;
        }
}

// ---------------- prep: parallel over (h, i) ----------------
__global__ void prep_kernel(const float* __restrict__ t_r, const float* __restrict__ t_t,
                            const float* __restrict__ gamma) {
    int idx = blockIdx.x * 256 + threadIdx.x;
    if (idx >= Hd * NN) return;
    int h = idx / NN, i = idx % NN;
    const float w_c = 0.23570226039551584f;
    float R[9], T[3];
#pragma unroll
    for (int r = 0; r < 9; ++r) R[r] = t_r[i * 9 + r];
#pragma unroll
    for (int c = 0; c < 3; ++c) T[c] = t_t[i * 3 + c];

    float x = gamma[h];
    float sp = (x > 20.f) ? x : log1pf(expf(x));
    float g = sp * w_c * 0.5f;

#pragma unroll
    for (int c = 0; c < Cd; ++c) {
        g_qe[(h * DE + c) * NN + i] = g_P[(      c * Hd + h) * NN + i] * 0.25f;
        g_ke[(h * DE + c) * NN + i] = g_P[(192 + c * Hd + h) * NN + i];
    }
    float qn = 0.f, kn = 0.f;
#pragma unroll
    for (int p = 0; p < PQd; ++p) {
        float q0 = g_P[(576 +  0 + h * 4 + p) * NN + i];
        float q1 = g_P[(576 + 48 + h * 4 + p) * NN + i];
        float q2 = g_P[(576 + 96 + h * 4 + p) * NN + i];
        float k0 = g_P[(720 +  0 + h * 4 + p) * NN + i];
        float k1 = g_P[(720 + 48 + h * 4 + p) * NN + i];
        float k2 = g_P[(720 + 96 + h * 4 + p) * NN + i];
#pragma unroll
        for (int co = 0; co < 3; ++co) {
            float qg = R[co * 3] * q0 + R[co * 3 + 1] * q1 + R[co * 3 + 2] * q2 + T[co];
            float kg = R[co * 3] * k0 + R[co * 3 + 1] * k1 + R[co * 3 + 2] * k2 + T[co];
            g_qe[(h * DE + 16 + co * 4 + p) * NN + i] = 2.f * g * qg;
            g_ke[(h * DE + 16 + co * 4 + p) * NN + i] = kg;
            qn += qg * qg;
            kn += kg * kg;
        }
    }
    g_qn[h * NN + i] = g * qn;
    g_kn[h * NN + i] = g * kn;

#pragma unroll
    for (int c = 0; c < Cd; ++c)
        g_vr[(h * Cd + c) * NN + i] = g_P[(384 + c * Hd + h) * NN + i];

#pragma unroll
    for (int p = 0; p < PVd; ++p) {
        float v0 = g_P[(864 +   0 + h * 8 + p) * NN + i];
        float v1 = g_P[(864 +  96 + h * 8 + p) * NN + i];
        float v2 = g_P[(864 + 192 + h * 8 + p) * NN + i];
#pragma unroll
        for (int co = 0; co < 3; ++co)
            g_vg[(co * 96 + h * 8 + p) * NN + i] =
                R[co * 3] * v0 + R[co * 3 + 1] * v1 + R[co * 3 + 2] * v2 + T[co];
    }
}

// ---------------- qk batched GEMM: Lqk[h] = qe[h]^T . ke[h] ----------------
__global__ __launch_bounds__(256) void qk_gemm() {
    __shared__ float As[32][64];
    __shared__ ull   Bs2[32][64];
    const int h = blockIdx.z, mb = blockIdx.y, nb = blockIdx.x;
    const float* Aq = g_qe + (size_t)h * DE * NN;
    const float* Bk = g_ke + (size_t)h * DE * NN;
    int tid = threadIdx.x, ty = tid >> 4, tx = tid & 15;

#pragma unroll
    for (int l = 0; l < 8; ++l) {
        int e = tid + l * 256, k = e >> 6, m = e & 63;
        if (k < DE) {
            As[k][m] = Aq[k * NN + mb * 64 + m];
            float v = Bk[k * NN + nb * 64 + m];
            Bs2[k][m] = pk2(v, v);
        }
    }
    __syncthreads();

    ull acc2[2][4];
#pragma unroll
    for (int u = 0; u < 2; ++u)
#pragma unroll
        for (int v = 0; v < 4; ++v) acc2[u][v] = 0ull;

#pragma unroll
    for (int k = 0; k < DE; ++k) {
        const ull* a2 = (const ull*)&As[k][ty * 4];
        ull a0 = a2[0], a1 = a2[1];
        ull b0 = Bs2[k][tx * 4], b1 = Bs2[k][tx * 4 + 1];
        ull b2 = Bs2[k][tx * 4 + 2], b3 = Bs2[k][tx * 4 + 3];
        ffma2(acc2[0][0], a0, b0); ffma2(acc2[0][1], a0, b1);
        ffma2(acc2[0][2], a0, b2); ffma2(acc2[0][3], a0, b3);
        ffma2(acc2[1][0], a1, b0); ffma2(acc2[1][1], a1, b1);
        ffma2(acc2[1][2], a1, b2); ffma2(acc2[1][3], a1, b3);
    }
    float* C = g_Lqk + (size_t)h * NN * NN;
#pragma unroll
    for (int u = 0; u < 2; ++u)
#pragma unroll
        for (int v = 0; v < 4; ++v) {
            float lo, hi;
            upk2(acc2[u][v], lo, hi);
            C[(size_t)(mb * 64 + ty * 4 + u * 2    ) * NN + nb * 64 + tx * 4 + v] = lo;
            C[(size_t)(mb * 64 + ty * 4 + u * 2 + 1) * NN + nb * 64 + tx * 4 + v] = hi;
        }
}

// ---------------- bias GEMM: [12h x 128c] @ z[c][n], single pass, deep MLP ----------------
__global__ __launch_bounds__(256, 2) void bias_kernel(const float* __restrict__ Z,
                                                      const float* __restrict__ Wb) {
    __shared__ ull W2s[CZd * Hd];
    const int tid = threadIdx.x;
    const size_t n4 = (size_t)blockIdx.x * 256 + tid;   // float4 index, 65536 total

    for (int e = tid; e < CZd * Hd; e += 256) {
        int c = e / 12, h = e % 12;
        float w = Wb[h * CZd + c];
        W2s[e] = pk2(w, w);
    }
    __syncthreads();

    ull acc[Hd][2];
#pragma unroll
    for (int h = 0; h < Hd; ++h) { acc[h][0] = 0ull; acc[h][1] = 0ull; }

    const float4* z4 = (const float4*)Z + n4;
    for (int cb = 0; cb < CZd; cb += 8) {
        float4 zv[8];
#pragma unroll
        for (int u = 0; u < 8; ++u)
            zv[u] = __ldg(&z4[(size_t)(cb + u) * 65536]);
#pragma unroll
        for (int u = 0; u < 8; ++u) {
            ull zx = pk2(zv[u].x, zv[u].y), zy = pk2(zv[u].z, zv[u].w);
#pragma unroll
            for (int h = 0; h < Hd; ++h) {
                ull w2 = W2s[(cb + u) * 12 + h];
                ffma2(acc[h][0], w2, zx);
                ffma2(acc[h][1], w2, zy);
            }
        }
    }

    float4* out4 = (float4*)g_bias;
#pragma unroll
    for (int h = 0; h < Hd; ++h) {
        float4 o;
        upk2(acc[h][0], o.x, o.y);
        upk2(acc[h][1], o.z, o.w);
        out4[(size_t)h * 65536 + n4] = o;
    }
}

// ---------------- logits + softmax -> probs g_A ----------------
__global__ __launch_bounds__(256) void logits2() {
    __shared__ float red[Hd][8];
    __shared__ float qns[Hd];
    const int i = blockIdx.x;
    const int tid = threadIdx.x;
    const int warp = tid >> 5, lane = tid & 31;
    const float w_l = 0.5773502691896258f;

    if (tid < 12) qns[tid] = g_qn[tid * NN + i];
    __syncthreads();

    float2 lv[Hd];
    size_t base = (size_t)i * NN + 2 * tid;
#pragma unroll
    for (int h = 0; h < Hd; ++h) {
        float2 b0 = *(const float2*)(g_bias + (size_t)h * NN * NN + base);
        float2 qk = *(const float2*)(g_Lqk + (size_t)h * NN * NN + base);
        float2 kn = *(const float2*)(g_kn + h * NN + 2 * tid);
        float qn = qns[h];
        lv[h].x = w_l * (b0.x + qk.x - qn - kn.x);
        lv[h].y = w_l * (b0.y + qk.y - qn - kn.y);
    }

#pragma unroll
    for (int h = 0; h < Hd; ++h) {
        float m = fmaxf(lv[h].x, lv[h].y);
#pragma unroll
        for (int o = 16; o; o >>= 1) m = fmaxf(m, __shfl_xor_sync(0xffffffffu, m, o));
        if (lane == 0) red[h][warp] = m;
    }
    __syncthreads();
    float mx[Hd];
#pragma unroll
    for (int h = 0; h < Hd; ++h) {
        float m = red[h][0];
#pragma unroll
        for (int w = 1; w < 8; ++w) m = fmaxf(m, red[h][w]);
        mx[h] = m;
    }
    __syncthreads();
#pragma unroll
    for (int h = 0; h < Hd; ++h) {
        lv[h].x = __expf(lv[h].x - mx[h]);
        lv[h].y = __expf(lv[h].y - mx[h]);
        float s = lv[h].x + lv[h].y;
#pragma unroll
        for (int o = 16; o; o >>= 1) s += __shfl_xor_sync(0xffffffffu, s, o);
        if (lane == 0) red[h][warp] = s;
    }
    __syncthreads();
    float* out = g_A + (size_t)i * Hd * NN;
#pragma unroll
    for (int h = 0; h < Hd; ++h) {
        float s = red[h][0];
#pragma unroll
        for (int w = 1; w < 8; ++w) s += red[h][w];
        float inv = 1.f / s;
        float2 p;
        p.x = lv[h].x * inv;
        p.y = lv[h].y * inv;
        *(float2*)(out + h * NN + 2 * tid) = p;
    }
}

// ---------------- o1: per (i, c-half), 2 c's per warp ----------------
__global__ __launch_bounds__(256) void o1k(const float* __restrict__ Z) {
    __shared__ ull Ps[Hd * 256];   // probs packed pairs, 24KB
    const int i = blockIdx.x;
    const int ks = blockIdx.y;
    const int tid = threadIdx.x;
    const int warp = tid >> 5, lane = tid & 31;

    {
        const ull* src = (const ull*)(g_A + (size_t)i * Hd * NN);
        for (int e = tid; e < Hd * 256; e += 256) Ps[e] = src[e];
    }
    __syncthreads();
    const ulonglong2* Ps2 = (const ulonglong2*)Ps;

#pragma unroll
    for (int cp = 0; cp < 4; ++cp) {
        const int c = ks * 64 + cp * 16 + warp * 2;
        const ulonglong2* zc0 = (const ulonglong2*)(Z + ((size_t)c * NN + i) * NN);
        const ulonglong2* zc1 = (const ulonglong2*)(Z + ((size_t)(c + 1) * NN + i) * NN);
        ull acc[Hd][2];
#pragma unroll
        for (int h = 0; h < Hd; ++h) { acc[h][0] = 0ull; acc[h][1] = 0ull; }
#pragma unroll
        for (int q = 0; q < 4; ++q) {
            ulonglong2 z0 = __ldg(&zc0[lane + 32 * q]);
            ulonglong2 z1 = __ldg(&zc1[lane + 32 * q]);
#pragma unroll
            for (int h = 0; h < Hd; ++h) {
                ulonglong2 pp = Ps2[h * 128 + lane + 32 * q];
                ffma2(acc[h][0], pp.x, z0.x);
                ffma2(acc[h][0], pp.y, z0.y);
                ffma2(acc[h][1], pp.x, z1.x);
                ffma2(acc[h][1], pp.y, z1.y);
            }
        }
#pragma unroll
        for (int h = 0; h < Hd; ++h) {
#pragma unroll
            for (int cc = 0; cc < 2; ++cc) {
                float lo, hi;
                upk2(acc[h][cc], lo, hi);
                float s = lo + hi;
#pragma unroll
                for (int o = 16; o; o >>= 1) s += __shfl_xor_sync(0xffffffffu, s, o);
                if (lane == 0) g_cat[(size_t)((c + cc) * Hd + h) * NN + i] = s;
            }
        }
    }
}

// ---------------- o2 + o3 (+ transform + norm): per i ----------------
__global__ __launch_bounds__(256) void o23k(const float* __restrict__ t_r,
                                            const float* __restrict__ t_t) {
    __shared__ ull Ps[Hd * 256];
    __shared__ float o3s[288];
    __shared__ float red[8];
    const int i = blockIdx.x;
    const int tid = threadIdx.x;
    const int warp = tid >> 5, lane = tid & 31;

    {
        const ull* src = (const ull*)(g_A + (size_t)i * Hd * NN);
        for (int e = tid; e < Hd * 256; e += 256) Ps[e] = src[e];
    }
    __syncthreads();
    const ulonglong2* Ps2 = (const ulonglong2*)Ps;

    for (int r = warp; r < 480; r += 8) {
        const ulonglong2* vrow;
        int h;
        if (r < 192) { vrow = (const ulonglong2*)(g_vr + (size_t)r * NN); h = r >> 4; }
        else { int rr = r - 192; vrow = (const ulonglong2*)(g_vg + (size_t)rr * NN); h = (rr % 96) >> 3; }
        ull s2 = 0ull;
#pragma unroll
        for (int q = 0; q < 4; ++q) {
            ulonglong2 vv = __ldg(&vrow[lane + 32 * q]);
            ulonglong2 pp = Ps2[h * 128 + lane + 32 * q];
            ffma2(s2, pp.x, vv.x);
            ffma2(s2, pp.y, vv.y);
        }
        float lo, hi;
        upk2(s2, lo, hi);
        float s = lo + hi;
#pragma unroll
        for (int o = 16; o; o >>= 1) s += __shfl_xor_sync(0xffffffffu, s, o);
        if (lane == 0) {
            if (r < 192) g_cat[(size_t)(1536 + (r & 15) * Hd + h) * NN + i] = s;
            else         o3s[r - 192] = s;
        }
    }
    __syncthreads();

    // inverse transform + write o3 + norm
    float R[9], T[3];
#pragma unroll
    for (int r = 0; r < 9; ++r) R[r] = t_r[i * 9 + r];
#pragma unroll
    for (int c = 0; c < 3; ++c) T[c] = t_t[i * 3 + c];

    float nloc = 0.f;
    for (int rr = tid; rr < 288; rr += 256) {
        int co = rr / 96, hp = rr % 96;
        float v = R[0 * 3 + co] * (o3s[0 * 96 + hp] - T[0])
                + R[1 * 3 + co] * (o3s[1 * 96 + hp] - T[1])
                + R[2 * 3 + co] * (o3s[2 * 96 + hp] - T[2]);
        g_cat[(size_t)(1728 + rr) * NN + i] = v;
        nloc += v * v;
    }
#pragma unroll
    for (int o = 16; o; o >>= 1) nloc += __shfl_xor_sync(0xffffffffu, nloc, o);
    if (lane == 0) red[warp] = nloc;
    __syncthreads();
    if (tid == 0) {
        float s = 0.f;
#pragma unroll
        for (int w = 0; w < 8; ++w) s += red[w];
        g_cat[(size_t)2016 * NN + i] = sqrtf(s);
    }
}

// ---------------- final reduce ----------------
__global__ void reduce_out(const float* __restrict__ bs, float* __restrict__ out) {
    int idx = blockIdx.x * 256 + threadIdx.x;
    if (idx >= CSd * NN) return;
    int o = idx >> 9;
    float v = bs[o];
#pragma unroll
    for (int zk = 0; zk < KSPLIT; ++zk) v += g_part[(size_t)zk * CSd * NN + idx];
    out[idx] = v;
}

// ---------------- launcher with capturable fork/join overlap ----------------
extern "C" void kernel_launch(void* const* d_in, const int* in_sizes, int n_in,
                              void* d_out, int out_size) {
    const float* s    = (const float*)d_in[0];
    const float* z    = (const float*)d_in[1];
    const float* t_r  = (const float*)d_in[2];
    const float* t_t  = (const float*)d_in[3];
    const float* Wq   = (const float*)d_in[4];
    const float* Wk   = (const float*)d_in[5];
    const float* Wv   = (const float*)d_in[6];
    const float* Wqp  = (const float*)d_in[7];
    const float* Wkp  = (const float*)d_in[8];
    const float* Wvp  = (const float*)d_in[9];
    const float* Wb   = (const float*)d_in[10];
    const float* gam  = (const float*)d_in[11];
    const float* Ws   = (const float*)d_in[12];
    const float* bs   = (const float*)d_in[13];
    float* out = (float*)d_out;

    float *pWcat, *pP, *pCat, *pPart;
    cudaGetSymbolAddress((void**)&pWcat, g_Wcat);
    cudaGetSymbolAddress((void**)&pP,    g_P);
    cudaGetSymbolAddress((void**)&pCat,  g_cat);
    cudaGetSymbolAddress((void**)&pPart, g_part);

    static cudaStream_t sB = nullptr;
    static cudaEvent_t evA = nullptr, evB = nullptr, evC = nullptr, evD = nullptr;
    if (!sB) {
        cudaStreamCreateWithFlags(&sB, cudaStreamNonBlocking);
        cudaEventCreateWithFlags(&evA, cudaEventDisableTiming);
        cudaEventCreateWithFlags(&evB, cudaEventDisableTiming);
        cudaEventCreateWithFlags(&evC, cudaEventDisableTiming);
        cudaEventCreateWithFlags(&evD, cudaEventDisableTiming);
    }

    // fork: bias (z stream) runs concurrently with projection chain
    cudaEventRecord(evA, 0);
    cudaStreamWaitEvent(sB, evA, 0);
    bias_kernel<<<256, 256, 0, sB>>>(z, Wb);
    cudaEventRecord(evB, sB);

    concat_w<<<(MPROJ * CSd + 255) / 256, 256>>>(Wq, Wk, Wv, Wqp, Wkp, Wvp);
    gemm64<<<dim3(NN / 64, MPROJ / 64, 1), 256>>>(pWcat, s, pP, MPROJ, NN, CSd);
    prep_kernel<<<(Hd * NN + 255) / 256, 256>>>(t_r, t_t, gam);
    qk_gemm<<<dim3(NN / 64, NN / 64, Hd), 256>>>();

    // join: logits needs bias + qk + prep
    cudaStreamWaitEvent(0, evB, 0);
    logits2<<<NN, 256>>>();

    // fork: o23k concurrent with o1k
    cudaEventRecord(evC, 0);
    cudaStreamWaitEvent(sB, evC, 0);
    o23k<<<NN, 256, 0, sB>>>(t_r, t_t);
    cudaEventRecord(evD, sB);

    o1k<<<dim3(NN, 2), 256>>>(z);

    // join: final GEMM needs all of g_cat
    cudaStreamWaitEvent(0, evD, 0);
    gemm64<<<dim3(NN / 64, CSd / 64, KSPLIT), 256>>>(Ws, pCat, pPart, CSd, NN, CATd);
    reduce_out<<<(CSd * NN + 255) / 256, 256>>>(bs, out);
}

// round 9
// speedup vs baseline: 1.0500x; 1.0500x over previous
#include <cuda_runtime.h>
#include <math.h>

#define NN   512
#define CSd  384
#define CZd  128
#define Hd   12
#define Cd   16
#define PQd  4
#define PVd  8
#define DE   28
#define CATd 2017
#define MPROJ 1152
#define KSPLIT 8

typedef unsigned long long ull;

// ---------------- packed f32x2 helpers ----------------
__device__ __forceinline__ void ffma2(ull& acc, ull a, ull b) {
    asm("fma.rn.f32x2 %0, %1, %2, %0;" : "+l"(acc) : "l"(a), "l"(b));
}
__device__ __forceinline__ ull pk2(float x, float y) {
    ull r; asm("mov.b64 %0, {%1,%2};" : "=l"(r) : "f"(x), "f"(y)); return r;
}
__device__ __forceinline__ void upk2(ull v, float& x, float& y) {
    asm("mov.b64 {%0,%1}, %2;" : "=f"(x), "=f"(y) : "l"(v));
}

// ---------------- device scratch ----------------
__device__ float g_Wcat[MPROJ * CSd];
__device__ float g_P[MPROJ * NN];
__device__ float g_qe[Hd * DE * NN];
__device__ float g_ke[Hd * DE * NN];
__device__ float g_qn[Hd * NN];
__device__ float g_kn[Hd * NN];
__device__ float g_vr[Hd * Cd * NN];
__device__ float g_vg[3 * Hd * PVd * NN];
__device__ float g_Lqk[Hd * NN * NN];        // qk - dist partial [h][i][j]
__device__ float g_A[NN * Hd * NN];          // probs [i][h][j]
__device__ float g_cat[CATd * NN];
__device__ float g_part[KSPLIT * CSd * NN];

// ---------------- weight concat ----------------
__global__ void concat_w(const float* __restrict__ Wq, const float* __restrict__ Wk,
                         const float* __restrict__ Wv, const float* __restrict__ Wqp,
                         const float* __restrict__ Wkp, const float* __restrict__ Wvp) {
    int idx = blockIdx.x * 256 + threadIdx.x;
    if (idx >= MPROJ * CSd) return;
    int row = idx / CSd, c = idx % CSd;
    float v;
    if      (row < 192) v = Wq [(row      ) * CSd + c];
    else if (row < 384) v = Wk [(row - 192) * CSd + c];
    else if (row < 576) v = Wv [(row - 384) * CSd + c];
    else if (row < 720) v = Wqp[(row - 576) * CSd + c];
    else if (row < 864) v = Wkp[(row - 720) * CSd + c];
    else                v = Wvp[(row - 864) * CSd + c];
    g_Wcat[idx] = v;
}

// ---------------- tiled GEMM with split-K, pre-packed B ----------------
__global__ __launch_bounds__(256) void gemm64(const float* __restrict__ A,
                                              const float* __restrict__ B,
                                              float* __restrict__ C,
                                              int M, int Nc, int K) {
    int nb = blockIdx.x, mb = blockIdx.y, zb = blockIdx.z;
    int Kc = (K + gridDim.z - 1) / gridDim.z;
    int k0 = zb * Kc;
    int kend = min(K, k0 + Kc);

    __shared__ float As[16][64];
    __shared__ ull   Bs2[16][64];

    int tid = threadIdx.x;
    int ty = tid >> 4, tx = tid & 15;
    ull acc2[2][4];
#pragma unroll
    for (int u = 0; u < 2; ++u)
#pragma unroll
        for (int v = 0; v < 4; ++v) acc2[u][v] = 0ull;

    for (int kk = k0; kk < kend; kk += 16) {
#pragma unroll
        for (int l = 0; l < 4; ++l) {
            int e = tid + l * 256;
            int m = e >> 4, k = e & 15;
            As[k][m] = (kk + k < kend) ? A[(size_t)(mb * 64 + m) * K + kk + k] : 0.f;
        }
#pragma unroll
        for (int l = 0; l < 4; ++l) {
            int e = tid + l * 256;
            int k = e >> 6, n = e & 63;
            float v = (kk + k < kend) ? B[(size_t)(kk + k) * Nc + nb * 64 + n] : 0.f;
            Bs2[k][n] = pk2(v, v);
        }
        __syncthreads();
#pragma unroll
        for (int k = 0; k < 16; ++k) {
            const ull* a2 = (const ull*)&As[k][ty * 4];
            ull a0 = a2[0], a1 = a2[1];
            ull b0 = Bs2[k][tx * 4], b1 = Bs2[k][tx * 4 + 1];
            ull b2 = Bs2[k][tx * 4 + 2], b3 = Bs2[k][tx * 4 + 3];
            ffma2(acc2[0][0], a0, b0); ffma2(acc2[0][1], a0, b1);
            ffma2(acc2[0][2], a0, b2); ffma2(acc2[0][3], a0, b3);
            ffma2(acc2[1][0], a1, b0); ffma2(acc2[1][1], a1, b1);
            ffma2(acc2[1][2], a1, b2); ffma2(acc2[1][3], a1, b3);
        }
        __syncthreads();
    }
    float* Cz = C + (size_t)zb * M * Nc;
#pragma unroll
    for (int u = 0; u < 2; ++u)
#pragma unroll
        for (int v = 0; v < 4; ++v) {
            float lo, hi;
            upk2(acc2[u][v], lo, hi);
            Cz[(size_t)(mb * 64 + ty * 4 + u * 2    ) * Nc + nb * 64 + tx * 4 + v] = lo;
            Cz[(size_t)(mb * 64 + ty * 4 + u * 2 + 1) * Nc + nb * 64 + tx * 4 + v] = hi;
        }
}

// ---------------- prep: parallel over (h, i), 128-thr blocks ----------------
__global__ __launch_bounds__(128) void prep_kernel(const float* __restrict__ t_r,
                                                   const float* __restrict__ t_t,
                                                   const float* __restrict__ gamma) {
    int idx = blockIdx.x * 128 + threadIdx.x;
    int h = idx >> 9, i = idx & 511;
    const float w_c = 0.23570226039551584f;
    float R[9], T[3];
#pragma unroll
    for (int r = 0; r < 9; ++r) R[r] = t_r[i * 9 + r];
#pragma unroll
    for (int c = 0; c < 3; ++c) T[c] = t_t[i * 3 + c];

    float x = gamma[h];
    float sp = (x > 20.f) ? x : log1pf(expf(x));
    float g = sp * w_c * 0.5f;

#pragma unroll
    for (int c = 0; c < Cd; ++c) {
        g_qe[(h * DE + c) * NN + i] = g_P[(      c * Hd + h) * NN + i] * 0.25f;
        g_ke[(h * DE + c) * NN + i] = g_P[(192 + c * Hd + h) * NN + i];
    }
    float qn = 0.f, kn = 0.f;
#pragma unroll
    for (int p = 0; p < PQd; ++p) {
        float q0 = g_P[(576 +  0 + h * 4 + p) * NN + i];
        float q1 = g_P[(576 + 48 + h * 4 + p) * NN + i];
        float q2 = g_P[(576 + 96 + h * 4 + p) * NN + i];
        float k0 = g_P[(720 +  0 + h * 4 + p) * NN + i];
        float k1 = g_P[(720 + 48 + h * 4 + p) * NN + i];
        float k2 = g_P[(720 + 96 + h * 4 + p) * NN + i];
#pragma unroll
        for (int co = 0; co < 3; ++co) {
            float qg = R[co * 3] * q0 + R[co * 3 + 1] * q1 + R[co * 3 + 2] * q2 + T[co];
            float kg = R[co * 3] * k0 + R[co * 3 + 1] * k1 + R[co * 3 + 2] * k2 + T[co];
            g_qe[(h * DE + 16 + co * 4 + p) * NN + i] = 2.f * g * qg;
            g_ke[(h * DE + 16 + co * 4 + p) * NN + i] = kg;
            qn += qg * qg;
            kn += kg * kg;
        }
    }
    g_qn[h * NN + i] = g * qn;
    g_kn[h * NN + i] = g * kn;

#pragma unroll
    for (int c = 0; c < Cd; ++c)
        g_vr[(h * Cd + c) * NN + i] = g_P[(384 + c * Hd + h) * NN + i];

#pragma unroll
    for (int p = 0; p < PVd; ++p) {
        float v0 = g_P[(864 +   0 + h * 8 + p) * NN + i];
        float v1 = g_P[(864 +  96 + h * 8 + p) * NN + i];
        float v2 = g_P[(864 + 192 + h * 8 + p) * NN + i];
#pragma unroll
        for (int co = 0; co < 3; ++co)
            g_vg[(co * 96 + h * 8 + p) * NN + i] =
                R[co * 3] * v0 + R[co * 3 + 1] * v1 + R[co * 3 + 2] * v2 + T[co];
    }
}

// ---------------- qk batched GEMM: Lqk[h] = qe[h]^T . ke[h] ----------------
__global__ __launch_bounds__(256) void qk_gemm() {
    __shared__ float As[32][64];
    __shared__ ull   Bs2[32][64];
    const int h = blockIdx.z, mb = blockIdx.y, nb = blockIdx.x;
    const float* Aq = g_qe + (size_t)h * DE * NN;
    const float* Bk = g_ke + (size_t)h * DE * NN;
    int tid = threadIdx.x, ty = tid >> 4, tx = tid & 15;

#pragma unroll
    for (int l = 0; l < 8; ++l) {
        int e = tid + l * 256, k = e >> 6, m = e & 63;
        if (k < DE) {
            As[k][m] = Aq[k * NN + mb * 64 + m];
            float v = Bk[k * NN + nb * 64 + m];
            Bs2[k][m] = pk2(v, v);
        }
    }
    __syncthreads();

    ull acc2[2][4];
#pragma unroll
    for (int u = 0; u < 2; ++u)
#pragma unroll
        for (int v = 0; v < 4; ++v) acc2[u][v] = 0ull;

#pragma unroll
    for (int k = 0; k < DE; ++k) {
        const ull* a2 = (const ull*)&As[k][ty * 4];
        ull a0 = a2[0], a1 = a2[1];
        ull b0 = Bs2[k][tx * 4], b1 = Bs2[k][tx * 4 + 1];
        ull b2 = Bs2[k][tx * 4 + 2], b3 = Bs2[k][tx * 4 + 3];
        ffma2(acc2[0][0], a0, b0); ffma2(acc2[0][1], a0, b1);
        ffma2(acc2[0][2], a0, b2); ffma2(acc2[0][3], a0, b3);
        ffma2(acc2[1][0], a1, b0); ffma2(acc2[1][1], a1, b1);
        ffma2(acc2[1][2], a1, b2); ffma2(acc2[1][3], a1, b3);
    }
    float* C = g_Lqk + (size_t)h * NN * NN;
#pragma unroll
    for (int u = 0; u < 2; ++u)
#pragma unroll
        for (int v = 0; v < 4; ++v) {
            float lo, hi;
            upk2(acc2[u][v], lo, hi);
            C[(size_t)(mb * 64 + ty * 4 + u * 2    ) * NN + nb * 64 + tx * 4 + v] = lo;
            C[(size_t)(mb * 64 + ty * 4 + u * 2 + 1) * NN + nb * 64 + tx * 4 + v] = hi;
        }
}

// ======== fused bias + logits + softmax: block = 2 query rows, writes probs ========
// Each block covers n4 in [b*256, b*256+256) float4 = 1024 floats = rows i0=2b, i0+1.
// tid 0..127 -> i0 (warps 0-3), tid 128..255 -> i0+1 (warps 4-7).
__global__ __launch_bounds__(256, 2) void bias_softmax_kernel(const float* __restrict__ Z,
                                                              const float* __restrict__ Wb) {
    __shared__ ull   W2s[CZd * Hd];
    __shared__ float redM[24][4];
    __shared__ float redS[24][4];
    __shared__ float qns[24];

    const int tid = threadIdx.x;
    const size_t n4 = (size_t)blockIdx.x * 256 + tid;   // float4 index
    const int half = tid >> 7;                           // which i
    const int i = blockIdx.x * 2 + half;
    const int j4 = tid & 127;                            // float4 index within row
    const int warpIn = (tid >> 5) & 3;
    const int lane = tid & 31;
    const float w_l = 0.5773502691896258f;

    for (int e = tid; e < CZd * Hd; e += 256) {
        int c = e / 12, h = e % 12;
        float w = Wb[h * CZd + c];
        W2s[e] = pk2(w, w);
    }
    if (tid < 24) qns[tid] = g_qn[(tid % 12) * NN + blockIdx.x * 2 + tid / 12];
    __syncthreads();

    ull acc[Hd][2];
#pragma unroll
    for (int h = 0; h < Hd; ++h) { acc[h][0] = 0ull; acc[h][1] = 0ull; }

    // ---- bias = Wb @ z, deep-MLP c loop ----
    const float4* z4 = (const float4*)Z + n4;
    for (int cb = 0; cb < CZd; cb += 8) {
        float4 zv[8];
#pragma unroll
        for (int u = 0; u < 8; ++u)
            zv[u] = __ldg(&z4[(size_t)(cb + u) * 65536]);
#pragma unroll
        for (int u = 0; u < 8; ++u) {
            ull zx = pk2(zv[u].x, zv[u].y), zy = pk2(zv[u].z, zv[u].w);
#pragma unroll
            for (int h = 0; h < Hd; ++h) {
                ull w2 = W2s[(cb + u) * 12 + h];
                ffma2(acc[h][0], w2, zx);
                ffma2(acc[h][1], w2, zy);
            }
        }
    }

    // ---- logits + warp-level max ----
#pragma unroll
    for (int h = 0; h < Hd; ++h) {
        float4 qk = __ldg((const float4*)g_Lqk + (size_t)h * 65536 + n4);
        float4 kn = __ldg((const float4*)g_kn + h * 128 + j4);
        float qn = qns[half * 12 + h];
        float a0, a1, a2, a3;
        upk2(acc[h][0], a0, a1);
        upk2(acc[h][1], a2, a3);
        a0 = w_l * (a0 + qk.x - qn - kn.x);
        a1 = w_l * (a1 + qk.y - qn - kn.y);
        a2 = w_l * (a2 + qk.z - qn - kn.z);
        a3 = w_l * (a3 + qk.w - qn - kn.w);
        acc[h][0] = pk2(a0, a1);
        acc[h][1] = pk2(a2, a3);
        float m = fmaxf(fmaxf(a0, a1), fmaxf(a2, a3));
#pragma unroll
        for (int o = 16; o; o >>= 1) m = fmaxf(m, __shfl_xor_sync(0xffffffffu, m, o));
        if (lane == 0) redM[half * 12 + h][warpIn] = m;
    }
    __syncthreads();

    // ---- exp + warp-level sum ----
#pragma unroll
    for (int h = 0; h < Hd; ++h) {
        const float* r = redM[half * 12 + h];
        float m = fmaxf(fmaxf(r[0], r[1]), fmaxf(r[2], r[3]));
        float a0, a1, a2, a3;
        upk2(acc[h][0], a0, a1);
        upk2(acc[h][1], a2, a3);
        a0 = __expf(a0 - m); a1 = __expf(a1 - m);
        a2 = __expf(a2 - m); a3 = __expf(a3 - m);
        acc[h][0] = pk2(a0, a1);
        acc[h][1] = pk2(a2, a3);
        float s = (a0 + a1) + (a2 + a3);
#pragma unroll
        for (int o = 16; o; o >>= 1) s += __shfl_xor_sync(0xffffffffu, s, o);
        if (lane == 0) redS[half * 12 + h][warpIn] = s;
    }
    __syncthreads();

    // ---- normalize + write probs ----
    float4* A4 = (float4*)g_A;
#pragma unroll
    for (int h = 0; h < Hd; ++h) {
        const float* r = redS[half * 12 + h];
        float inv = 1.f / ((r[0] + r[1]) + (r[2] + r[3]));
        float a0, a1, a2, a3;
        upk2(acc[h][0], a0, a1);
        upk2(acc[h][1], a2, a3);
        float4 p;
        p.x = a0 * inv; p.y = a1 * inv; p.z = a2 * inv; p.w = a3 * inv;
        A4[(size_t)i * 1536 + h * 128 + j4] = p;
    }
}

// ---------------- o1: per (i, c-half), 2 c's per warp, staged z ----------------
__global__ __launch_bounds__(256) void o1k(const float* __restrict__ Z) {
    __shared__ ull Ps[Hd * 256];   // probs packed pairs, 24KB
    const int i = blockIdx.x;
    const int ks = blockIdx.y;
    const int tid = threadIdx.x;
    const int warp = tid >> 5, lane = tid & 31;

    {
        const ull* src = (const ull*)(g_A + (size_t)i * Hd * NN);
        for (int e = tid; e < Hd * 256; e += 256) Ps[e] = src[e];
    }
    __syncthreads();
    const ulonglong2* Ps2 = (const ulonglong2*)Ps;

#pragma unroll
    for (int cp = 0; cp < 4; ++cp) {
        const int c = ks * 64 + cp * 16 + warp * 2;
        const ulonglong2* zc0 = (const ulonglong2*)(Z + ((size_t)c * NN + i) * NN);
        const ulonglong2* zc1 = (const ulonglong2*)(Z + ((size_t)(c + 1) * NN + i) * NN);
        ulonglong2 z0[4], z1[4];
#pragma unroll
        for (int q = 0; q < 4; ++q) {
            z0[q] = __ldg(&zc0[lane + 32 * q]);
            z1[q] = __ldg(&zc1[lane + 32 * q]);
        }
        ull acc[Hd][2];
#pragma unroll
        for (int h = 0; h < Hd; ++h) { acc[h][0] = 0ull; acc[h][1] = 0ull; }
#pragma unroll
        for (int q = 0; q < 4; ++q) {
#pragma unroll
            for (int h = 0; h < Hd; ++h) {
                ulonglong2 pp = Ps2[h * 128 + lane + 32 * q];
                ffma2(acc[h][0], pp.x, z0[q].x);
                ffma2(acc[h][0], pp.y, z0[q].y);
                ffma2(acc[h][1], pp.x, z1[q].x);
                ffma2(acc[h][1], pp.y, z1[q].y);
            }
        }
#pragma unroll
        for (int h = 0; h < Hd; ++h) {
#pragma unroll
            for (int cc = 0; cc < 2; ++cc) {
                float lo, hi;
                upk2(acc[h][cc], lo, hi);
                float s = lo + hi;
#pragma unroll
                for (int o = 16; o; o >>= 1) s += __shfl_xor_sync(0xffffffffu, s, o);
                if (lane == 0) g_cat[(size_t)((c + cc) * Hd + h) * NN + i] = s;
            }
        }
    }
}

// ---------------- o2 + o3 (+ transform + norm): per i ----------------
__global__ __launch_bounds__(256) void o23k(const float* __restrict__ t_r,
                                            const float* __restrict__ t_t) {
    __shared__ ull Ps[Hd * 256];
    __shared__ float o3s[288];
    __shared__ float red[8];
    const int i = blockIdx.x;
    const int tid = threadIdx.x;
    const int warp = tid >> 5, lane = tid & 31;

    {
        const ull* src = (const ull*)(g_A + (size_t)i * Hd * NN);
        for (int e = tid; e < Hd * 256; e += 256) Ps[e] = src[e];
    }
    __syncthreads();
    const ulonglong2* Ps2 = (const ulonglong2*)Ps;

    for (int r = warp; r < 480; r += 8) {
        const ulonglong2* vrow;
        int h;
        if (r < 192) { vrow = (const ulonglong2*)(g_vr + (size_t)r * NN); h = r >> 4; }
        else { int rr = r - 192; vrow = (const ulonglong2*)(g_vg + (size_t)rr * NN); h = (rr % 96) >> 3; }
        ull s2 = 0ull;
#pragma unroll
        for (int q = 0; q < 4; ++q) {
            ulonglong2 vv = __ldg(&vrow[lane + 32 * q]);
            ulonglong2 pp = Ps2[h * 128 + lane + 32 * q];
            ffma2(s2, pp.x, vv.x);
            ffma2(s2, pp.y, vv.y);
        }
        float lo, hi;
        upk2(s2, lo, hi);
        float s = lo + hi;
#pragma unroll
        for (int o = 16; o; o >>= 1) s += __shfl_xor_sync(0xffffffffu, s, o);
        if (lane == 0) {
            if (r < 192) g_cat[(size_t)(1536 + (r & 15) * Hd + h) * NN + i] = s;
            else         o3s[r - 192] = s;
        }
    }
    __syncthreads();

    float R[9], T[3];
#pragma unroll
    for (int r = 0; r < 9; ++r) R[r] = t_r[i * 9 + r];
#pragma unroll
    for (int c = 0; c < 3; ++c) T[c] = t_t[i * 3 + c];

    float nloc = 0.f;
    for (int rr = tid; rr < 288; rr += 256) {
        int co = rr / 96, hp = rr % 96;
        float v = R[0 * 3 + co] * (o3s[0 * 96 + hp] - T[0])
                + R[1 * 3 + co] * (o3s[1 * 96 + hp] - T[1])
                + R[2 * 3 + co] * (o3s[2 * 96 + hp] - T[2]);
        g_cat[(size_t)(1728 + rr) * NN + i] = v;
        nloc += v * v;
    }
#pragma unroll
    for (int o = 16; o; o >>= 1) nloc += __shfl_xor_sync(0xffffffffu, nloc, o);
    if (lane == 0) red[warp] = nloc;
    __syncthreads();
    if (tid == 0) {
        float s = 0.f;
#pragma unroll
        for (int w = 0; w < 8; ++w) s += red[w];
        g_cat[(size_t)2016 * NN + i] = sqrtf(s);
    }
}

// ---------------- final reduce ----------------
__global__ void reduce_out(const float* __restrict__ bs, float* __restrict__ out) {
    int idx = blockIdx.x * 256 + threadIdx.x;
    if (idx >= CSd * NN) return;
    int o = idx >> 9;
    float v = bs[o];
#pragma unroll
    for (int zk = 0; zk < KSPLIT; ++zk) v += g_part[(size_t)zk * CSd * NN + idx];
    out[idx] = v;
}

// ---------------- launcher (serial) ----------------
extern "C" void kernel_launch(void* const* d_in, const int* in_sizes, int n_in,
                              void* d_out, int out_size) {
    const float* s    = (const float*)d_in[0];
    const float* z    = (const float*)d_in[1];
    const float* t_r  = (const float*)d_in[2];
    const float* t_t  = (const float*)d_in[3];
    const float* Wq   = (const float*)d_in[4];
    const float* Wk   = (const float*)d_in[5];
    const float* Wv   = (const float*)d_in[6];
    const float* Wqp  = (const float*)d_in[7];
    const float* Wkp  = (const float*)d_in[8];
    const float* Wvp  = (const float*)d_in[9];
    const float* Wb   = (const float*)d_in[10];
    const float* gam  = (const float*)d_in[11];
    const float* Ws   = (const float*)d_in[12];
    const float* bs   = (const float*)d_in[13];
    float* out = (float*)d_out;

    float *pWcat, *pP, *pCat, *pPart;
    cudaGetSymbolAddress((void**)&pWcat, g_Wcat);
    cudaGetSymbolAddress((void**)&pP,    g_P);
    cudaGetSymbolAddress((void**)&pCat,  g_cat);
    cudaGetSymbolAddress((void**)&pPart, g_part);

    concat_w<<<(MPROJ * CSd + 255) / 256, 256>>>(Wq, Wk, Wv, Wqp, Wkp, Wvp);
    gemm64<<<dim3(NN / 64, MPROJ / 64, 1), 256>>>(pWcat, s, pP, MPROJ, NN, CSd);
    prep_kernel<<<Hd * NN / 128, 128>>>(t_r, t_t, gam);
    qk_gemm<<<dim3(NN / 64, NN / 64, Hd), 256>>>();
    bias_softmax_kernel<<<256, 256>>>(z, Wb);
    o1k<<<dim3(NN, 2), 256>>>(z);
    o23k<<<NN, 256>>>(t_r, t_t);
    gemm64<<<dim3(NN / 64, CSd / 64, KSPLIT), 256>>>(Ws, pCat, pPart, CSd, NN, CATd);
    reduce_out<<<(CSd * NN + 255) / 256, 256>>>(bs, out);
}

// round 10
// speedup vs baseline: 1.0867x; 1.0349x over previous
#include <cuda_runtime.h>
#include <math.h>

#define NN   512
#define CSd  384
#define CZd  128
#define Hd   12
#define Cd   16
#define PQd  4
#define PVd  8
#define DE   28
#define CATd 2017
#define MPROJ 1152
#define KSPLIT 8

typedef unsigned long long ull;

// ---------------- packed f32x2 helpers ----------------
__device__ __forceinline__ void ffma2(ull& acc, ull a, ull b) {
    asm("fma.rn.f32x2 %0, %1, %2, %0;" : "+l"(acc) : "l"(a), "l"(b));
}
__device__ __forceinline__ ull pk2(float x, float y) {
    ull r; asm("mov.b64 %0, {%1,%2};" : "=l"(r) : "f"(x), "f"(y)); return r;
}
__device__ __forceinline__ void upk2(ull v, float& x, float& y) {
    asm("mov.b64 {%0,%1}, %2;" : "=f"(x), "=f"(y) : "l"(v));
}

// ---------------- device scratch ----------------
__device__ float g_P[MPROJ * NN];
__device__ float g_qe[Hd * DE * NN];
__device__ float g_ke[Hd * DE * NN];
__device__ float g_qn[Hd * NN];
__device__ float g_kn[Hd * NN];
__device__ float g_vr[Hd * Cd * NN];
__device__ float g_vg[3 * Hd * PVd * NN];
__device__ float g_Lqk[Hd * NN * NN];        // qk - dist partial [h][i][j]
__device__ float g_A[NN * Hd * NN];          // probs [i][h][j]
__device__ float g_cat[CATd * NN];
__device__ float g_part[KSPLIT * CSd * NN];

// ---------------- projection GEMM with fused weight concat ----------------
// C = Wcat(1152x384) @ s(384x512); Wcat rows map to the 6 weight tensors.
__global__ __launch_bounds__(256) void proj_gemm(const float* __restrict__ s,
                                                 const float* __restrict__ Wq,
                                                 const float* __restrict__ Wk,
                                                 const float* __restrict__ Wv,
                                                 const float* __restrict__ Wqp,
                                                 const float* __restrict__ Wkp,
                                                 const float* __restrict__ Wvp) {
    __shared__ float As[16][64];
    __shared__ ull   Bs2[16][64];

    const int nb = blockIdx.x, mb = blockIdx.y;
    const int tid = threadIdx.x;
    const int ty = tid >> 4, tx = tid & 15;

    // precompute source row pointers (constant across k loop)
    const float* rowp[4];
#pragma unroll
    for (int l = 0; l < 4; ++l) {
        int e = tid + l * 256;
        int r = mb * 64 + (e >> 4);
        const float* p;
        if      (r < 192) p = Wq  + (size_t)r * CSd;
        else if (r < 384) p = Wk  + (size_t)(r - 192) * CSd;
        else if (r < 576) p = Wv  + (size_t)(r - 384) * CSd;
        else if (r < 720) p = Wqp + (size_t)(r - 576) * CSd;
        else if (r < 864) p = Wkp + (size_t)(r - 720) * CSd;
        else              p = Wvp + (size_t)(r - 864) * CSd;
        rowp[l] = p;
    }

    ull acc2[2][4];
#pragma unroll
    for (int u = 0; u < 2; ++u)
#pragma unroll
        for (int v = 0; v < 4; ++v) acc2[u][v] = 0ull;

    for (int kk = 0; kk < CSd; kk += 16) {
#pragma unroll
        for (int l = 0; l < 4; ++l) {
            int e = tid + l * 256;
            As[e & 15][e >> 4] = rowp[l][kk + (e & 15)];
        }
#pragma unroll
        for (int l = 0; l < 4; ++l) {
            int e = tid + l * 256;
            int k = e >> 6, n = e & 63;
            float v = s[(size_t)(kk + k) * NN + nb * 64 + n];
            Bs2[k][n] = pk2(v, v);
        }
        __syncthreads();
#pragma unroll
        for (int k = 0; k < 16; ++k) {
            const ull* a2 = (const ull*)&As[k][ty * 4];
            ull a0 = a2[0], a1 = a2[1];
            ull b0 = Bs2[k][tx * 4], b1 = Bs2[k][tx * 4 + 1];
            ull b2 = Bs2[k][tx * 4 + 2], b3 = Bs2[k][tx * 4 + 3];
            ffma2(acc2[0][0], a0, b0); ffma2(acc2[0][1], a0, b1);
            ffma2(acc2[0][2], a0, b2); ffma2(acc2[0][3], a0, b3);
            ffma2(acc2[1][0], a1, b0); ffma2(acc2[1][1], a1, b1);
            ffma2(acc2[1][2], a1, b2); ffma2(acc2[1][3], a1, b3);
        }
        __syncthreads();
    }
#pragma unroll
    for (int u = 0; u < 2; ++u)
#pragma unroll
        for (int v = 0; v < 4; ++v) {
            float lo, hi;
            upk2(acc2[u][v], lo, hi);
            g_P[(size_t)(mb * 64 + ty * 4 + u * 2    ) * NN + nb * 64 + tx * 4 + v] = lo;
            g_P[(size_t)(mb * 64 + ty * 4 + u * 2 + 1) * NN + nb * 64 + tx * 4 + v] = hi;
        }
}

// ---------------- generic tiled GEMM with split-K (final GEMM) ----------------
__global__ __launch_bounds__(256) void gemm64(const float* __restrict__ A,
                                              const float* __restrict__ B,
                                              float* __restrict__ C,
                                              int M, int Nc, int K) {
    int nb = blockIdx.x, mb = blockIdx.y, zb = blockIdx.z;
    int Kc = (K + gridDim.z - 1) / gridDim.z;
    int k0 = zb * Kc;
    int kend = min(K, k0 + Kc);

    __shared__ float As[16][64];
    __shared__ ull   Bs2[16][64];

    int tid = threadIdx.x;
    int ty = tid >> 4, tx = tid & 15;
    ull acc2[2][4];
#pragma unroll
    for (int u = 0; u < 2; ++u)
#pragma unroll
        for (int v = 0; v < 4; ++v) acc2[u][v] = 0ull;

    for (int kk = k0; kk < kend; kk += 16) {
#pragma unroll
        for (int l = 0; l < 4; ++l) {
            int e = tid + l * 256;
            int m = e >> 4, k = e & 15;
            As[k][m] = (kk + k < kend) ? A[(size_t)(mb * 64 + m) * K + kk + k] : 0.f;
        }
#pragma unroll
        for (int l = 0; l < 4; ++l) {
            int e = tid + l * 256;
            int k = e >> 6, n = e & 63;
            float v = (kk + k < kend) ? B[(size_t)(kk + k) * Nc + nb * 64 + n] : 0.f;
            Bs2[k][n] = pk2(v, v);
        }
        __syncthreads();
#pragma unroll
        for (int k = 0; k < 16; ++k) {
            const ull* a2 = (const ull*)&As[k][ty * 4];
            ull a0 = a2[0], a1 = a2[1];
            ull b0 = Bs2[k][tx * 4], b1 = Bs2[k][tx * 4 + 1];
            ull b2 = Bs2[k][tx * 4 + 2], b3 = Bs2[k][tx * 4 + 3];
            ffma2(acc2[0][0], a0, b0); ffma2(acc2[0][1], a0, b1);
            ffma2(acc2[0][2], a0, b2); ffma2(acc2[0][3], a0, b3);
            ffma2(acc2[1][0], a1, b0); ffma2(acc2[1][1], a1, b1);
            ffma2(acc2[1][2], a1, b2); ffma2(acc2[1][3], a1, b3);
        }
        __syncthreads();
    }
    float* Cz = C + (size_t)zb * M * Nc;
#pragma unroll
    for (int u = 0; u < 2; ++u)
#pragma unroll
        for (int v = 0; v < 4; ++v) {
            float lo, hi;
            upk2(acc2[u][v], lo, hi);
            Cz[(size_t)(mb * 64 + ty * 4 + u * 2    ) * Nc + nb * 64 + tx * 4 + v] = lo;
            Cz[(size_t)(mb * 64 + ty * 4 + u * 2 + 1) * Nc + nb * 64 + tx * 4 + v] = hi;
        }
}

// ---------------- prep: parallel over (h, i), 128-thr blocks ----------------
__global__ __launch_bounds__(128) void prep_kernel(const float* __restrict__ t_r,
                                                   const float* __restrict__ t_t,
                                                   const float* __restrict__ gamma) {
    int idx = blockIdx.x * 128 + threadIdx.x;
    int h = idx >> 9, i = idx & 511;
    const float w_c = 0.23570226039551584f;
    float R[9], T[3];
#pragma unroll
    for (int r = 0; r < 9; ++r) R[r] = t_r[i * 9 + r];
#pragma unroll
    for (int c = 0; c < 3; ++c) T[c] = t_t[i * 3 + c];

    float x = gamma[h];
    float sp = (x > 20.f) ? x : log1pf(expf(x));
    float g = sp * w_c * 0.5f;

#pragma unroll
    for (int c = 0; c < Cd; ++c) {
        g_qe[(h * DE + c) * NN + i] = g_P[(      c * Hd + h) * NN + i] * 0.25f;
        g_ke[(h * DE + c) * NN + i] = g_P[(192 + c * Hd + h) * NN + i];
    }
    float qn = 0.f, kn = 0.f;
#pragma unroll
    for (int p = 0; p < PQd; ++p) {
        float q0 = g_P[(576 +  0 + h * 4 + p) * NN + i];
        float q1 = g_P[(576 + 48 + h * 4 + p) * NN + i];
        float q2 = g_P[(576 + 96 + h * 4 + p) * NN + i];
        float k0 = g_P[(720 +  0 + h * 4 + p) * NN + i];
        float k1 = g_P[(720 + 48 + h * 4 + p) * NN + i];
        float k2 = g_P[(720 + 96 + h * 4 + p) * NN + i];
#pragma unroll
        for (int co = 0; co < 3; ++co) {
            float qg = R[co * 3] * q0 + R[co * 3 + 1] * q1 + R[co * 3 + 2] * q2 + T[co];
            float kg = R[co * 3] * k0 + R[co * 3 + 1] * k1 + R[co * 3 + 2] * k2 + T[co];
            g_qe[(h * DE + 16 + co * 4 + p) * NN + i] = 2.f * g * qg;
            g_ke[(h * DE + 16 + co * 4 + p) * NN + i] = kg;
            qn += qg * qg;
            kn += kg * kg;
        }
    }
    g_qn[h * NN + i] = g * qn;
    g_kn[h * NN + i] = g * kn;

#pragma unroll
    for (int c = 0; c < Cd; ++c)
        g_vr[(h * Cd + c) * NN + i] = g_P[(384 + c * Hd + h) * NN + i];

#pragma unroll
    for (int p = 0; p < PVd; ++p) {
        float v0 = g_P[(864 +   0 + h * 8 + p) * NN + i];
        float v1 = g_P[(864 +  96 + h * 8 + p) * NN + i];
        float v2 = g_P[(864 + 192 + h * 8 + p) * NN + i];
#pragma unroll
        for (int co = 0; co < 3; ++co)
            g_vg[(co * 96 + h * 8 + p) * NN + i] =
                R[co * 3] * v0 + R[co * 3 + 1] * v1 + R[co * 3 + 2] * v2 + T[co];
    }
}

// ---------------- qk batched GEMM: Lqk[h] = qe[h]^T . ke[h] ----------------
__global__ __launch_bounds__(256) void qk_gemm() {
    __shared__ float As[32][64];
    __shared__ ull   Bs2[32][64];
    const int h = blockIdx.z, mb = blockIdx.y, nb = blockIdx.x;
    const float* Aq = g_qe + (size_t)h * DE * NN;
    const float* Bk = g_ke + (size_t)h * DE * NN;
    int tid = threadIdx.x, ty = tid >> 4, tx = tid & 15;

#pragma unroll
    for (int l = 0; l < 8; ++l) {
        int e = tid + l * 256, k = e >> 6, m = e & 63;
        if (k < DE) {
            As[k][m] = Aq[k * NN + mb * 64 + m];
            float v = Bk[k * NN + nb * 64 + m];
            Bs2[k][m] = pk2(v, v);
        }
    }
    __syncthreads();

    ull acc2[2][4];
#pragma unroll
    for (int u = 0; u < 2; ++u)
#pragma unroll
        for (int v = 0; v < 4; ++v) acc2[u][v] = 0ull;

#pragma unroll
    for (int k = 0; k < DE; ++k) {
        const ull* a2 = (const ull*)&As[k][ty * 4];
        ull a0 = a2[0], a1 = a2[1];
        ull b0 = Bs2[k][tx * 4], b1 = Bs2[k][tx * 4 + 1];
        ull b2 = Bs2[k][tx * 4 + 2], b3 = Bs2[k][tx * 4 + 3];
        ffma2(acc2[0][0], a0, b0); ffma2(acc2[0][1], a0, b1);
        ffma2(acc2[0][2], a0, b2); ffma2(acc2[0][3], a0, b3);
        ffma2(acc2[1][0], a1, b0); ffma2(acc2[1][1], a1, b1);
        ffma2(acc2[1][2], a1, b2); ffma2(acc2[1][3], a1, b3);
    }
    float* C = g_Lqk + (size_t)h * NN * NN;
#pragma unroll
    for (int u = 0; u < 2; ++u)
#pragma unroll
        for (int v = 0; v < 4; ++v) {
            float lo, hi;
            upk2(acc2[u][v], lo, hi);
            C[(size_t)(mb * 64 + ty * 4 + u * 2    ) * NN + nb * 64 + tx * 4 + v] = lo;
            C[(size_t)(mb * 64 + ty * 4 + u * 2 + 1) * NN + nb * 64 + tx * 4 + v] = hi;
        }
}

// ======== fused bias + logits + softmax v2: ONE query row per block ========
// 256 threads = 128 j4-columns x 2 c-halves. c-half partials combined via smem.
__global__ __launch_bounds__(256, 2) void bias_softmax_kernel(const float* __restrict__ Z,
                                                              const float* __restrict__ Wb) {
    __shared__ ull   W2s[CZd * Hd];        // 12288 B
    __shared__ ull   part[Hd * 256];       // 24576 B : [h][pair(2)][j4(128)]
    __shared__ float redM[Hd][4];
    __shared__ float redS[Hd][4];
    __shared__ float qns[Hd];

    const int tid = threadIdx.x;
    const int i = blockIdx.x;
    const int j4 = tid & 127;               // float4 column within row
    const int ch = tid >> 7;                // c-half
    const int warpIn = tid >> 5;            // 0..7 (only 0..3 used in softmax)
    const int lane = tid & 31;
    const float w_l = 0.5773502691896258f;

    for (int e = tid; e < CZd * Hd; e += 256) {
        int c = e / 12, h = e % 12;
        float w = Wb[h * CZd + c];
        W2s[e] = pk2(w, w);
    }
    if (tid < 12) qns[tid] = g_qn[tid * NN + i];
    __syncthreads();

    ull acc[Hd][2];
#pragma unroll
    for (int h = 0; h < Hd; ++h) { acc[h][0] = 0ull; acc[h][1] = 0ull; }

    // ---- bias partial over this thread's 64 c's ----
    const float4* z4 = (const float4*)Z + (size_t)i * 128 + j4;
    const int c0 = ch * 64;
    for (int cb = 0; cb < 64; cb += 8) {
        float4 zv[8];
#pragma unroll
        for (int u = 0; u < 8; ++u)
            zv[u] = __ldg(&z4[(size_t)(c0 + cb + u) * 65536]);
#pragma unroll
        for (int u = 0; u < 8; ++u) {
            ull zx = pk2(zv[u].x, zv[u].y), zy = pk2(zv[u].z, zv[u].w);
#pragma unroll
            for (int h = 0; h < Hd; ++h) {
                ull w2 = W2s[(c0 + cb + u) * 12 + h];
                ffma2(acc[h][0], w2, zx);
                ffma2(acc[h][1], w2, zy);
            }
        }
    }

    // ---- combine halves ----
    if (ch == 1) {
#pragma unroll
        for (int h = 0; h < Hd; ++h) {
            part[h * 256 + j4]       = acc[h][0];
            part[h * 256 + 128 + j4] = acc[h][1];
        }
    }
    __syncthreads();

    if (ch == 0) {
#pragma unroll
        for (int h = 0; h < Hd; ++h) {
            float a0, a1, b0, b1;
            upk2(acc[h][0], a0, a1);
            upk2(part[h * 256 + j4], b0, b1);
            float c0f = a0 + b0, c1f = a1 + b1;
            upk2(acc[h][1], a0, a1);
            upk2(part[h * 256 + 128 + j4], b0, b1);
            float c2f = a0 + b0, c3f = a1 + b1;

            float4 qk = __ldg((const float4*)g_Lqk + (size_t)h * 65536 + (size_t)i * 128 + j4);
            float4 kn = __ldg((const float4*)g_kn + h * 128 + j4);
            float qn = qns[h];
            c0f = w_l * (c0f + qk.x - qn - kn.x);
            c1f = w_l * (c1f + qk.y - qn - kn.y);
            c2f = w_l * (c2f + qk.z - qn - kn.z);
            c3f = w_l * (c3f + qk.w - qn - kn.w);
            acc[h][0] = pk2(c0f, c1f);
            acc[h][1] = pk2(c2f, c3f);
            float m = fmaxf(fmaxf(c0f, c1f), fmaxf(c2f, c3f));
#pragma unroll
            for (int o = 16; o; o >>= 1) m = fmaxf(m, __shfl_xor_sync(0xffffffffu, m, o));
            if (lane == 0) redM[h][warpIn] = m;
        }
    }
    __syncthreads();

    if (ch == 0) {
#pragma unroll
        for (int h = 0; h < Hd; ++h) {
            const float* r = redM[h];
            float m = fmaxf(fmaxf(r[0], r[1]), fmaxf(r[2], r[3]));
            float a0, a1, a2, a3;
            upk2(acc[h][0], a0, a1);
            upk2(acc[h][1], a2, a3);
            a0 = __expf(a0 - m); a1 = __expf(a1 - m);
            a2 = __expf(a2 - m); a3 = __expf(a3 - m);
            acc[h][0] = pk2(a0, a1);
            acc[h][1] = pk2(a2, a3);
            float s = (a0 + a1) + (a2 + a3);
#pragma unroll
            for (int o = 16; o; o >>= 1) s += __shfl_xor_sync(0xffffffffu, s, o);
            if (lane == 0) redS[h][warpIn] = s;
        }
    }
    __syncthreads();

    if (ch == 0) {
        float4* A4 = (float4*)g_A;
#pragma unroll
        for (int h = 0; h < Hd; ++h) {
            const float* r = redS[h];
            float inv = 1.f / ((r[0] + r[1]) + (r[2] + r[3]));
            float a0, a1, a2, a3;
            upk2(acc[h][0], a0, a1);
            upk2(acc[h][1], a2, a3);
            float4 p;
            p.x = a0 * inv; p.y = a1 * inv; p.z = a2 * inv; p.w = a3 * inv;
            A4[(size_t)i * 1536 + h * 128 + j4] = p;
        }
    }
}

// ---------------- o1: per (i, c-half), 2 c's per warp, staged z ----------------
__global__ __launch_bounds__(256) void o1k(const float* __restrict__ Z) {
    __shared__ ull Ps[Hd * 256];   // probs packed pairs, 24KB
    const int i = blockIdx.x;
    const int ks = blockIdx.y;
    const int tid = threadIdx.x;
    const int warp = tid >> 5, lane = tid & 31;

    {
        const ull* src = (const ull*)(g_A + (size_t)i * Hd * NN);
        for (int e = tid; e < Hd * 256; e += 256) Ps[e] = src[e];
    }
    __syncthreads();
    const ulonglong2* Ps2 = (const ulonglong2*)Ps;

#pragma unroll
    for (int cp = 0; cp < 4; ++cp) {
        const int c = ks * 64 + cp * 16 + warp * 2;
        const ulonglong2* zc0 = (const ulonglong2*)(Z + ((size_t)c * NN + i) * NN);
        const ulonglong2* zc1 = (const ulonglong2*)(Z + ((size_t)(c + 1) * NN + i) * NN);
        ulonglong2 z0[4], z1[4];
#pragma unroll
        for (int q = 0; q < 4; ++q) {
            z0[q] = __ldg(&zc0[lane + 32 * q]);
            z1[q] = __ldg(&zc1[lane + 32 * q]);
        }
        ull acc[Hd][2];
#pragma unroll
        for (int h = 0; h < Hd; ++h) { acc[h][0] = 0ull; acc[h][1] = 0ull; }
#pragma unroll
        for (int q = 0; q < 4; ++q) {
#pragma unroll
            for (int h = 0; h < Hd; ++h) {
                ulonglong2 pp = Ps2[h * 128 + lane + 32 * q];
                ffma2(acc[h][0], pp.x, z0[q].x);
                ffma2(acc[h][0], pp.y, z0[q].y);
                ffma2(acc[h][1], pp.x, z1[q].x);
                ffma2(acc[h][1], pp.y, z1[q].y);
            }
        }
#pragma unroll
        for (int h = 0; h < Hd; ++h) {
#pragma unroll
            for (int cc = 0; cc < 2; ++cc) {
                float lo, hi;
                upk2(acc[h][cc], lo, hi);
                float s = lo + hi;
#pragma unroll
                for (int o = 16; o; o >>= 1) s += __shfl_xor_sync(0xffffffffu, s, o);
                if (lane == 0) g_cat[(size_t)((c + cc) * Hd + h) * NN + i] = s;
            }
        }
    }
}

// ---------------- o2 + o3 (+ transform + norm): 2 query rows per block ----------------
__global__ __launch_bounds__(256) void o23k(const float* __restrict__ t_r,
                                            const float* __restrict__ t_t) {
    __shared__ ull Ps[2 * Hd * 256];   // 48KB
    __shared__ float o3s[2][288];
    __shared__ float red[2][8];
    const int i0 = blockIdx.x * 2;
    const int tid = threadIdx.x;
    const int warp = tid >> 5, lane = tid & 31;

    {
        const ull* src = (const ull*)(g_A + (size_t)i0 * Hd * NN);
        for (int e = tid; e < 2 * Hd * 256; e += 256) Ps[e] = src[e];
    }
    __syncthreads();
    const ulonglong2* Ps2 = (const ulonglong2*)Ps;

    for (int r = warp; r < 480; r += 8) {
        const ulonglong2* vrow;
        int h;
        if (r < 192) { vrow = (const ulonglong2*)(g_vr + (size_t)r * NN); h = r >> 4; }
        else { int rr = r - 192; vrow = (const ulonglong2*)(g_vg + (size_t)rr * NN); h = (rr % 96) >> 3; }
        ull s0 = 0ull, s1 = 0ull;
#pragma unroll
        for (int q = 0; q < 4; ++q) {
            ulonglong2 vv = __ldg(&vrow[lane + 32 * q]);
            ulonglong2 p0 = Ps2[h * 128 + lane + 32 * q];
            ulonglong2 p1 = Ps2[(Hd + h) * 128 + lane + 32 * q];
            ffma2(s0, p0.x, vv.x);
            ffma2(s0, p0.y, vv.y);
            ffma2(s1, p1.x, vv.x);
            ffma2(s1, p1.y, vv.y);
        }
        float lo, hi;
        upk2(s0, lo, hi);
        float sa = lo + hi;
        upk2(s1, lo, hi);
        float sb = lo + hi;
#pragma unroll
        for (int o = 16; o; o >>= 1) {
            sa += __shfl_xor_sync(0xffffffffu, sa, o);
            sb += __shfl_xor_sync(0xffffffffu, sb, o);
        }
        if (lane == 0) {
            if (r < 192) {
                g_cat[(size_t)(1536 + (r & 15) * Hd + h) * NN + i0]     = sa;
                g_cat[(size_t)(1536 + (r & 15) * Hd + h) * NN + i0 + 1] = sb;
            } else {
                o3s[0][r - 192] = sa;
                o3s[1][r - 192] = sb;
            }
        }
    }
    __syncthreads();

    // inverse transform + norm for both rows (threads split: tid<128 -> i0, else i0+1... use loop)
    for (int ii = 0; ii < 2; ++ii) {
        int i = i0 + ii;
        float R[9], T[3];
#pragma unroll
        for (int r = 0; r < 9; ++r) R[r] = t_r[i * 9 + r];
#pragma unroll
        for (int c = 0; c < 3; ++c) T[c] = t_t[i * 3 + c];

        float nloc = 0.f;
        for (int rr = tid; rr < 288; rr += 256) {
            int co = rr / 96, hp = rr % 96;
            float v = R[0 * 3 + co] * (o3s[ii][0 * 96 + hp] - T[0])
                    + R[1 * 3 + co] * (o3s[ii][1 * 96 + hp] - T[1])
                    + R[2 * 3 + co] * (o3s[ii][2 * 96 + hp] - T[2]);
            g_cat[(size_t)(1728 + rr) * NN + i] = v;
            nloc += v * v;
        }
#pragma unroll
        for (int o = 16; o; o >>= 1) nloc += __shfl_xor_sync(0xffffffffu, nloc, o);
        if (lane == 0) red[ii][warp] = nloc;
    }
    __syncthreads();
    if (tid < 2) {
        float s = 0.f;
#pragma unroll
        for (int w = 0; w < 8; ++w) s += red[tid][w];
        g_cat[(size_t)2016 * NN + i0 + tid] = sqrtf(s);
    }
}

// ---------------- final reduce ----------------
__global__ void reduce_out(const float* __restrict__ bs, float* __restrict__ out) {
    int idx = blockIdx.x * 256 + threadIdx.x;
    if (idx >= CSd * NN) return;
    int o = idx >> 9;
    float v = bs[o];
#pragma unroll
    for (int zk = 0; zk < KSPLIT; ++zk) v += g_part[(size_t)zk * CSd * NN + idx];
    out[idx] = v;
}

// ---------------- launcher (serial) ----------------
extern "C" void kernel_launch(void* const* d_in, const int* in_sizes, int n_in,
                              void* d_out, int out_size) {
    const float* s    = (const float*)d_in[0];
    const float* z    = (const float*)d_in[1];
    const float* t_r  = (const float*)d_in[2];
    const float* t_t  = (const float*)d_in[3];
    const float* Wq   = (const float*)d_in[4];
    const float* Wk   = (const float*)d_in[5];
    const float* Wv   = (const float*)d_in[6];
    const float* Wqp  = (const float*)d_in[7];
    const float* Wkp  = (const float*)d_in[8];
    const float* Wvp  = (const float*)d_in[9];
    const float* Wb   = (const float*)d_in[10];
    const float* gam  = (const float*)d_in[11];
    const float* Ws   = (const float*)d_in[12];
    const float* bs   = (const float*)d_in[13];
    float* out = (float*)d_out;

    float *pCat, *pPart;
    cudaGetSymbolAddress((void**)&pCat,  g_cat);
    cudaGetSymbolAddress((void**)&pPart, g_part);

    proj_gemm<<<dim3(NN / 64, MPROJ / 64), 256>>>(s, Wq, Wk, Wv, Wqp, Wkp, Wvp);
    prep_kernel<<<Hd * NN / 128, 128>>>(t_r, t_t, gam);
    qk_gemm<<<dim3(NN / 64, NN / 64, Hd), 256>>>();
    bias_softmax_kernel<<<NN, 256>>>(z, Wb);
    o1k<<<dim3(NN, 2), 256>>>(z);
    o23k<<<NN / 2, 256>>>(t_r, t_t);
    gemm64<<<dim3(NN / 64, CSd / 64, KSPLIT), 256>>>(Ws, pCat, pPart, CSd, NN, CATd);
    reduce_out<<<(CSd * NN + 255) / 256, 256>>>(bs, out);
}